// round 4
// baseline (speedup 1.0000x reference)
#include <cuda_runtime.h>
#include <cuda_bf16.h>
#include <math.h>

#define BQ 8
#define TT 512
#define CC 512
#define HH 8
#define DHD 64
#define LL 2
#define MM (BQ * TT)
#define STEPS 4

#define O_X   0LL
#define O_XN  2097152LL
#define O_Q   4194304LL
#define O_K   6291456LL
#define O_V   8388608LL
#define O_Y   10485760LL
#define O_H   12582912LL
#define O_ATT 20971520LL
#define N_SCR 37748736LL

__device__ __align__(16) float g_scratch[N_SCR];

__device__ __forceinline__ void bsplit(float v, __nv_bfloat16 &h, __nv_bfloat16 &l) {
    h = __float2bfloat16(v);
    l = __float2bfloat16(v - __bfloat162float(h));
}

__device__ __forceinline__ void mma_bf16(float *d, const unsigned *a, unsigned b0, unsigned b1) {
    asm volatile(
        "mma.sync.aligned.m16n8k16.row.col.f32.bf16.bf16.f32 "
        "{%0,%1,%2,%3}, {%4,%5,%6,%7}, {%8,%9}, {%0,%1,%2,%3};\n"
        : "+f"(d[0]), "+f"(d[1]), "+f"(d[2]), "+f"(d[3])
        : "r"(a[0]), "r"(a[1]), "r"(a[2]), "r"(a[3]), "r"(b0), "r"(b1));
}

__device__ __forceinline__ float gelu_exact(float x) {
    return 0.5f * x * (1.0f + erff(x * 0.7071067811865476f));
}

// Generic batched GEMM, split-bf16 (3 MMAs => ~fp32 accuracy).
// C = A[M,K] @ B (+bias). transB=0: B row-major [K,N]; transB=1: C = A @ B^T, B [N,K].
// Batch z: ptr += (z/zdiv)*s?0 + (z%zdiv)*s?1.
// ep: 0 store, 1 gelu(acc+bias), 2 C += acc+bias.
// Tiles 64x64x32, 256 thr (8 warps, warp tile 16x32). M,N %64==0, K %32==0.
#define GP 34
__global__ __launch_bounds__(256)
void gemm_kernel(const float *__restrict__ A, int lda, long long sA0, long long sA1,
                 const float *__restrict__ B, int ldb, long long sB0, long long sB1,
                 float *__restrict__ C, int ldc, long long sC0, long long sC1,
                 int K, int zdiv, const float *__restrict__ bias, int transB, int ep)
{
    int z = blockIdx.z;
    A += (long long)(z / zdiv) * sA0 + (long long)(z % zdiv) * sA1;
    B += (long long)(z / zdiv) * sB0 + (long long)(z % zdiv) * sB1;
    C += (long long)(z / zdiv) * sC0 + (long long)(z % zdiv) * sC1;
    int n0 = blockIdx.x * 64, m0 = blockIdx.y * 64;

    __shared__ __align__(16) __nv_bfloat16 Ah[64][GP], Al[64][GP], Bh[64][GP], Bl[64][GP];

    int t = threadIdx.x, lane = t & 31, warp = t >> 5;
    int wm = (warp & 3) << 4, wn = (warp >> 2) << 5;
    int gg = lane >> 2, cc2 = (lane & 3) << 1;

    float acc[4][4];
#pragma unroll
    for (int i = 0; i < 4; i++)
#pragma unroll
        for (int j = 0; j < 4; j++) acc[i][j] = 0.f;

    for (int k0 = 0; k0 < K; k0 += 32) {
        {
            int kq = (t & 7) << 2, mb = t >> 3;
#pragma unroll
            for (int p = 0; p < 2; p++) {
                int m = mb + (p << 5);
                float4 vv = *(const float4 *)(A + (long long)(m0 + m) * lda + (k0 + kq));
                __nv_bfloat16 h, l;
                bsplit(vv.x, h, l); Ah[m][kq] = h;     Al[m][kq] = l;
                bsplit(vv.y, h, l); Ah[m][kq + 1] = h; Al[m][kq + 1] = l;
                bsplit(vv.z, h, l); Ah[m][kq + 2] = h; Al[m][kq + 2] = l;
                bsplit(vv.w, h, l); Ah[m][kq + 3] = h; Al[m][kq + 3] = l;
            }
        }
        if (transB) {
            int kq = (t & 7) << 2, nb = t >> 3;
#pragma unroll
            for (int p = 0; p < 2; p++) {
                int n = nb + (p << 5);
                float4 vv = *(const float4 *)(B + (long long)(n0 + n) * ldb + (k0 + kq));
                __nv_bfloat16 h, l;
                bsplit(vv.x, h, l); Bh[n][kq] = h;     Bl[n][kq] = l;
                bsplit(vv.y, h, l); Bh[n][kq + 1] = h; Bl[n][kq + 1] = l;
                bsplit(vv.z, h, l); Bh[n][kq + 2] = h; Bl[n][kq + 2] = l;
                bsplit(vv.w, h, l); Bh[n][kq + 3] = h; Bl[n][kq + 3] = l;
            }
        } else {
            int nq = (t & 15) << 2, kb = t >> 4;
#pragma unroll
            for (int p = 0; p < 2; p++) {
                int kk = kb + (p << 4);
                float4 vv = *(const float4 *)(B + (long long)(k0 + kk) * ldb + (n0 + nq));
                __nv_bfloat16 h, l;
                bsplit(vv.x, h, l); Bh[nq][kk] = h;     Bl[nq][kk] = l;
                bsplit(vv.y, h, l); Bh[nq + 1][kk] = h; Bl[nq + 1][kk] = l;
                bsplit(vv.z, h, l); Bh[nq + 2][kk] = h; Bl[nq + 2][kk] = l;
                bsplit(vv.w, h, l); Bh[nq + 3][kk] = h; Bl[nq + 3][kk] = l;
            }
        }
        __syncthreads();

#pragma unroll
        for (int ks = 0; ks < 2; ks++) {
            int kb = ks << 4;
            unsigned ah[4], al[4];
            ah[0] = *(const unsigned *)&Ah[wm + gg][kb + cc2];
            ah[1] = *(const unsigned *)&Ah[wm + gg + 8][kb + cc2];
            ah[2] = *(const unsigned *)&Ah[wm + gg][kb + cc2 + 8];
            ah[3] = *(const unsigned *)&Ah[wm + gg + 8][kb + cc2 + 8];
            al[0] = *(const unsigned *)&Al[wm + gg][kb + cc2];
            al[1] = *(const unsigned *)&Al[wm + gg + 8][kb + cc2];
            al[2] = *(const unsigned *)&Al[wm + gg][kb + cc2 + 8];
            al[3] = *(const unsigned *)&Al[wm + gg + 8][kb + cc2 + 8];
#pragma unroll
            for (int j = 0; j < 4; j++) {
                int n = wn + (j << 3) + gg;
                unsigned bh0 = *(const unsigned *)&Bh[n][kb + cc2];
                unsigned bh1 = *(const unsigned *)&Bh[n][kb + cc2 + 8];
                unsigned bl0 = *(const unsigned *)&Bl[n][kb + cc2];
                unsigned bl1 = *(const unsigned *)&Bl[n][kb + cc2 + 8];
                mma_bf16(acc[j], ah, bh0, bh1);
                mma_bf16(acc[j], ah, bl0, bl1);
                mma_bf16(acc[j], al, bh0, bh1);
            }
        }
        __syncthreads();
    }

#pragma unroll
    for (int j = 0; j < 4; j++) {
        int col = n0 + wn + (j << 3) + cc2;
        int row = m0 + wm + gg;
        float b0v = bias ? bias[col] : 0.f;
        float b1v = bias ? bias[col + 1] : 0.f;
        float v00 = acc[j][0] + b0v, v01 = acc[j][1] + b1v;
        float v10 = acc[j][2] + b0v, v11 = acc[j][3] + b1v;
        float *p0 = C + (long long)row * ldc + col;
        float *p1 = C + (long long)(row + 8) * ldc + col;
        if (ep == 1) {
            v00 = gelu_exact(v00); v01 = gelu_exact(v01);
            v10 = gelu_exact(v10); v11 = gelu_exact(v11);
        } else if (ep == 2) {
            v00 += p0[0]; v01 += p0[1]; v10 += p1[0]; v11 += p1[1];
        }
        p0[0] = v00; p0[1] = v01; p1[0] = v10; p1[1] = v11;
    }
}

__global__ void embed_kernel(const int *__restrict__ idx, const float *__restrict__ tok,
                             const float *__restrict__ pos, float *__restrict__ x)
{
    int i = blockIdx.x * 256 + threadIdx.x;
    if (i >= MM * CC) return;
    int c = i & (CC - 1);
    int bt = i >> 9;
    int tp = bt & (TT - 1);
    x[i] = tok[idx[bt] * CC + c] + pos[tp * CC + c];
}

__global__ __launch_bounds__(256)
void ln_kernel(const float *__restrict__ x, float *__restrict__ o,
               const float *__restrict__ gam, const float *__restrict__ bet)
{
    __shared__ float red[256];
    int row = blockIdx.x, t = threadIdx.x;
    const float *xr = x + (long long)row * CC;
    float a = xr[t], b = xr[t + 256];
    red[t] = a + b;
    __syncthreads();
    for (int off = 128; off > 0; off >>= 1) {
        if (t < off) red[t] += red[t + off];
        __syncthreads();
    }
    float mu = red[0] * (1.0f / CC);
    __syncthreads();
    float da = a - mu, db = b - mu;
    red[t] = da * da + db * db;
    __syncthreads();
    for (int off = 128; off > 0; off >>= 1) {
        if (t < off) red[t] += red[t + off];
        __syncthreads();
    }
    float rstd = rsqrtf(red[0] * (1.0f / CC) + 1e-5f);
    float *orow = o + (long long)row * CC;
    orow[t]       = da * rstd * gam[t] + bet[t];
    orow[t + 256] = db * rstd * gam[t + 256] + bet[t + 256];
}

__global__ __launch_bounds__(128)
void softmax_kernel(float *__restrict__ att)
{
    __shared__ float red[128];
    int row = blockIdx.x, t = threadIdx.x;
    float *p = att + (long long)row * TT;
    float v[4];
    float m = -1e30f;
#pragma unroll
    for (int i = 0; i < 4; i++) { v[i] = p[t + (i << 7)] * 0.125f; m = fmaxf(m, v[i]); }
    red[t] = m; __syncthreads();
    for (int off = 64; off > 0; off >>= 1) {
        if (t < off) red[t] = fmaxf(red[t], red[t + off]);
        __syncthreads();
    }
    m = red[0]; __syncthreads();
    float s = 0.f;
#pragma unroll
    for (int i = 0; i < 4; i++) { v[i] = __expf(v[i] - m); s += v[i]; }
    red[t] = s; __syncthreads();
    for (int off = 64; off > 0; off >>= 1) {
        if (t < off) red[t] += red[t + off];
        __syncthreads();
    }
    float inv = 1.0f / red[0];
#pragma unroll
    for (int i = 0; i < 4; i++) p[t + (i << 7)] = v[i] * inv;
}

static inline void run_gemm(const float *A, int lda, long long sA0, long long sA1,
                            const float *B, int ldb, long long sB0, long long sB1,
                            float *C, int ldc, long long sC0, long long sC1,
                            int Mr, int Nc, int K, int zdiv, int batches,
                            const float *bias, int transB, int ep)
{
    dim3 grid(Nc / 64, Mr / 64, batches);
    gemm_kernel<<<grid, 256>>>(A, lda, sA0, sA1, B, ldb, sB0, sB1,
                               C, ldc, sC0, sC1, K, zdiv, bias, transB, ep);
}

extern "C" void kernel_launch(void *const *d_in, const int *in_sizes, int n_in,
                              void *d_out, int out_size)
{
    (void)in_sizes; (void)n_in; (void)out_size;
    const int   *idx  = (const int *)d_in[0];
    const float *tok  = (const float *)d_in[1];
    const float *pos  = (const float *)d_in[2];
    const float *ln1g = (const float *)d_in[3];
    const float *ln1b = (const float *)d_in[4];
    const float *Wq   = (const float *)d_in[5];
    const float *bq   = (const float *)d_in[6];
    const float *Wk   = (const float *)d_in[7];
    const float *bk   = (const float *)d_in[8];
    const float *Wv   = (const float *)d_in[9];
    const float *bv   = (const float *)d_in[10];
    const float *Wp   = (const float *)d_in[11];
    const float *bp   = (const float *)d_in[12];
    const float *ln2g = (const float *)d_in[13];
    const float *ln2b = (const float *)d_in[14];
    const float *W1   = (const float *)d_in[15];
    const float *b1   = (const float *)d_in[16];
    const float *W2   = (const float *)d_in[17];
    const float *b2   = (const float *)d_in[18];
    const float *lnfg = (const float *)d_in[19];
    const float *lnfb = (const float *)d_in[20];
    const float *Wh   = (const float *)d_in[21];
    float *out = (float *)d_out;

    float *S = nullptr;
    cudaGetSymbolAddress((void **)&S, g_scratch);
    float *x = S + O_X, *xn = S + O_XN, *q = S + O_Q, *k = S + O_K;
    float *v = S + O_V, *y = S + O_Y, *h = S + O_H, *att = S + O_ATT;

    embed_kernel<<<(MM * CC + 255) / 256, 256>>>(idx, tok, pos, x);

    const long long TC = (long long)TT * CC;
    const long long T2 = (long long)TT * TT;
    const long long HT2 = (long long)HH * T2;
    const long long CC2 = (long long)CC * CC;

    for (int s = 0; s < STEPS; s++) {
        for (int l = 0; l < LL; l++) {
            ln_kernel<<<MM, 256>>>(x, xn, ln1g + l * CC, ln1b + l * CC);
            run_gemm(xn, CC, 0, 0, Wq + l * CC2, CC, 0, 0, q, CC, 0, 0,
                     MM, CC, CC, 1, 1, bq + l * CC, 0, 0);
            run_gemm(xn, CC, 0, 0, Wk + l * CC2, CC, 0, 0, k, CC, 0, 0,
                     MM, CC, CC, 1, 1, bk + l * CC, 0, 0);
            run_gemm(xn, CC, 0, 0, Wv + l * CC2, CC, 0, 0, v, CC, 0, 0,
                     MM, CC, CC, 1, 1, bv + l * CC, 0, 0);
            // scores = Q @ K^T per (b,h): z = b*H + h
            run_gemm(q, CC, TC, DHD, k, CC, TC, DHD, att, TT, HT2, T2,
                     TT, TT, DHD, HH, BQ * HH, nullptr, 1, 0);
            softmax_kernel<<<BQ * HH * TT, 128>>>(att);
            // y = P @ V
            run_gemm(att, TT, HT2, T2, v, CC, TC, DHD, y, CC, TC, DHD,
                     TT, DHD, TT, HH, BQ * HH, nullptr, 0, 0);
            // x += y @ Wp + bp
            run_gemm(y, CC, 0, 0, Wp + l * CC2, CC, 0, 0, x, CC, 0, 0,
                     MM, CC, CC, 1, 1, bp + l * CC, 0, 2);
            ln_kernel<<<MM, 256>>>(x, xn, ln2g + l * CC, ln2b + l * CC);
            // h = gelu(xn @ W1 + b1)
            run_gemm(xn, CC, 0, 0, W1 + (long long)l * CC * 4 * CC, 4 * CC, 0, 0,
                     h, 4 * CC, 0, 0, MM, 4 * CC, CC, 1, 1, b1 + l * 4 * CC, 0, 1);
            // x += h @ W2 + b2
            run_gemm(h, 4 * CC, 0, 0, W2 + (long long)l * 4 * CC * CC, CC, 0, 0,
                     x, CC, 0, 0, MM, CC, 4 * CC, 1, 1, b2 + l * CC, 0, 2);
        }
    }
    ln_kernel<<<MM, 256>>>(x, xn, lnfg, lnfb);
    run_gemm(xn, CC, 0, 0, Wh, CC, 0, 0, out, CC, 0, 0,
             MM, CC, CC, 1, 1, nullptr, 0, 0);
}

// round 5
// speedup vs baseline: 1.4970x; 1.4970x over previous
#include <cuda_runtime.h>
#include <cuda_bf16.h>
#include <math.h>

#define BQ 8
#define TT 512
#define CC 512
#define HH 8
#define DHD 64
#define LL 2
#define MM (BQ * TT)
#define STEPS 4

#define O_X   0LL
#define O_XN  2097152LL
#define O_Q   4194304LL
#define O_K   6291456LL
#define O_V   8388608LL
#define O_Y   10485760LL
#define O_H   12582912LL
#define O_ATT 20971520LL
#define N_SCR 37748736LL

__device__ __align__(16) float g_scratch[N_SCR];

// pack two fp32 into bf16x2 hi + bf16x2 lo (split-bf16: ~fp32 accuracy via 3 MMAs)
__device__ __forceinline__ void split2(float x, float y, unsigned &hi, unsigned &lo) {
    __nv_bfloat16 hx = __float2bfloat16(x), hy = __float2bfloat16(y);
    __nv_bfloat16 lx = __float2bfloat16(x - __bfloat162float(hx));
    __nv_bfloat16 ly = __float2bfloat16(y - __bfloat162float(hy));
    hi = ((unsigned)__bfloat16_as_ushort(hy) << 16) | (unsigned)__bfloat16_as_ushort(hx);
    lo = ((unsigned)__bfloat16_as_ushort(ly) << 16) | (unsigned)__bfloat16_as_ushort(lx);
}

__device__ __forceinline__ void mma_bf16(float *d, const unsigned *a, unsigned b0, unsigned b1) {
    asm volatile(
        "mma.sync.aligned.m16n8k16.row.col.f32.bf16.bf16.f32 "
        "{%0,%1,%2,%3}, {%4,%5,%6,%7}, {%8,%9}, {%0,%1,%2,%3};\n"
        : "+f"(d[0]), "+f"(d[1]), "+f"(d[2]), "+f"(d[3])
        : "r"(a[0]), "r"(a[1]), "r"(a[2]), "r"(a[3]), "r"(b0), "r"(b1));
}

#define LDSM4(R0, R1, R2, R3, ADDR) \
    asm volatile("ldmatrix.sync.aligned.m8n8.x4.shared.b16 {%0,%1,%2,%3}, [%4];" \
                 : "=r"(R0), "=r"(R1), "=r"(R2), "=r"(R3) : "r"(ADDR))
#define LDSM4T(R0, R1, R2, R3, ADDR) \
    asm volatile("ldmatrix.sync.aligned.m8n8.x4.trans.shared.b16 {%0,%1,%2,%3}, [%4];" \
                 : "=r"(R0), "=r"(R1), "=r"(R2), "=r"(R3) : "r"(ADDR))

__device__ __forceinline__ unsigned smem_u32(const void *p) {
    return (unsigned)__cvta_generic_to_shared(p);
}

__device__ __forceinline__ float gelu_exact(float x) {
    return 0.5f * x * (1.0f + erff(x * 0.7071067811865476f));
}

// ---------------------------------------------------------------------------
// Generic batched GEMM, split-bf16, block tile 128x64, K-tile 32, 8 warps
// (warp tile 32x32). Fragments via ldmatrix(.trans); packed 8B smem stores;
// register-staged global prefetch.
// C = A[M,K] @ B (+bias). transB=0: B row-major [K,N]; transB=1: C = A @ B^T.
// Batch z: ptr += (z/zdiv)*s?0 + (z%zdiv)*s?1.
// ep: 0 store, 1 gelu(acc+bias), 2 C += acc+bias.
// Requires M%128==0, N%64==0, K%32==0.
// ---------------------------------------------------------------------------
#define APITCH 40   // A smem row pitch (bf16), 80B: 16B-aligned rows
#define BPT    40   // B smem pitch for transB=1 layout [n][k]
#define BPN    72   // B smem pitch for transB=0 layout [k][n], 144B rows

__global__ __launch_bounds__(256)
void gemm_kernel(const float *__restrict__ A, int lda, long long sA0, long long sA1,
                 const float *__restrict__ B, int ldb, long long sB0, long long sB1,
                 float *__restrict__ C, int ldc, long long sC0, long long sC1,
                 int K, int zdiv, const float *__restrict__ bias, int transB, int ep)
{
    int z = blockIdx.z;
    A += (long long)(z / zdiv) * sA0 + (long long)(z % zdiv) * sA1;
    B += (long long)(z / zdiv) * sB0 + (long long)(z % zdiv) * sB1;
    C += (long long)(z / zdiv) * sC0 + (long long)(z % zdiv) * sC1;
    int n0 = blockIdx.x * 64, m0 = blockIdx.y * 128;

    __shared__ __align__(16) __nv_bfloat16 sAh[128 * APITCH], sAl[128 * APITCH];
    __shared__ __align__(16) __nv_bfloat16 sBh[2560], sBl[2560];

    int t = threadIdx.x, lane = t & 31, warp = t >> 5;
    int wm = (warp & 3) << 5, wn = (warp >> 2) << 5;
    int gg = lane >> 2, cc2 = (lane & 3) << 1;

    // global staging indices
    int akq = (t & 7) << 2, amb = t >> 3;     // A: rows amb+32p (p<4), cols akq..+3
    int bnq = (t & 15) << 2, bkb = t >> 4;    // transB=0: k rows bkb+16p (p<2)
    // transB=1 uses akq/amb pattern on [N,K]

    // ldmatrix per-lane geometry
    int sel = lane >> 3, lr = lane & 7;
    int a_row = lr + ((sel & 1) ? 8 : 0);     // + wm + 16*mi ; col + ((sel&2)?8:0)
    int a_cs  = (sel & 2) ? 8 : 0;
    int bt_row = lr + ((sel & 2) ? 8 : 0);    // transB=1 [n][k]
    int bt_cs  = (sel & 1) ? 8 : 0;
    int bn_row = lr + ((sel & 1) ? 8 : 0);    // transB=0 [k][n] (trans ldmatrix)
    int bn_cs  = (sel & 2) ? 8 : 0;

    unsigned baseAh = smem_u32(sAh), baseAl = smem_u32(sAl);
    unsigned baseBh = smem_u32(sBh), baseBl = smem_u32(sBl);

    float acc[2][4][4];
#pragma unroll
    for (int mi = 0; mi < 2; mi++)
#pragma unroll
        for (int j = 0; j < 4; j++)
#pragma unroll
            for (int r = 0; r < 4; r++) acc[mi][j][r] = 0.f;

    float4 ar[4], br[2];
#pragma unroll
    for (int p = 0; p < 4; p++)
        ar[p] = *(const float4 *)(A + (long long)(m0 + amb + 32 * p) * lda + akq);
    if (transB) {
#pragma unroll
        for (int p = 0; p < 2; p++)
            br[p] = *(const float4 *)(B + (long long)(n0 + amb + 32 * p) * ldb + akq);
    } else {
#pragma unroll
        for (int p = 0; p < 2; p++)
            br[p] = *(const float4 *)(B + (long long)(bkb + 16 * p) * ldb + n0 + bnq);
    }

    for (int k0 = 0; k0 < K; k0 += 32) {
        // convert + store staged regs to smem (packed 8B stores)
#pragma unroll
        for (int p = 0; p < 4; p++) {
            unsigned h0, l0, h1, l1;
            split2(ar[p].x, ar[p].y, h0, l0);
            split2(ar[p].z, ar[p].w, h1, l1);
            int m = amb + 32 * p;
            *(uint2 *)&sAh[m * APITCH + akq] = make_uint2(h0, h1);
            *(uint2 *)&sAl[m * APITCH + akq] = make_uint2(l0, l1);
        }
        if (transB) {
#pragma unroll
            for (int p = 0; p < 2; p++) {
                unsigned h0, l0, h1, l1;
                split2(br[p].x, br[p].y, h0, l0);
                split2(br[p].z, br[p].w, h1, l1);
                int n = amb + 32 * p;
                *(uint2 *)&sBh[n * BPT + akq] = make_uint2(h0, h1);
                *(uint2 *)&sBl[n * BPT + akq] = make_uint2(l0, l1);
            }
        } else {
#pragma unroll
            for (int p = 0; p < 2; p++) {
                unsigned h0, l0, h1, l1;
                split2(br[p].x, br[p].y, h0, l0);
                split2(br[p].z, br[p].w, h1, l1);
                int kk = bkb + 16 * p;
                *(uint2 *)&sBh[kk * BPN + bnq] = make_uint2(h0, h1);
                *(uint2 *)&sBl[kk * BPN + bnq] = make_uint2(l0, l1);
            }
        }
        __syncthreads();

        if (k0 + 32 < K) {
            int kn = k0 + 32;
#pragma unroll
            for (int p = 0; p < 4; p++)
                ar[p] = *(const float4 *)(A + (long long)(m0 + amb + 32 * p) * lda + kn + akq);
            if (transB) {
#pragma unroll
                for (int p = 0; p < 2; p++)
                    br[p] = *(const float4 *)(B + (long long)(n0 + amb + 32 * p) * ldb + kn + akq);
            } else {
#pragma unroll
                for (int p = 0; p < 2; p++)
                    br[p] = *(const float4 *)(B + (long long)(kn + bkb + 16 * p) * ldb + n0 + bnq);
            }
        }

#pragma unroll
        for (int ks = 0; ks < 2; ks++) {
            int kb = ks << 4;
            unsigned ah[2][4], alr[2][4];
#pragma unroll
            for (int mi = 0; mi < 2; mi++) {
                unsigned off = (unsigned)(((wm + 16 * mi + a_row) * APITCH + kb + a_cs) * 2);
                LDSM4(ah[mi][0], ah[mi][1], ah[mi][2], ah[mi][3], baseAh + off);
                LDSM4(alr[mi][0], alr[mi][1], alr[mi][2], alr[mi][3], baseAl + off);
            }
            unsigned bh[4][2], blr[4][2];
#pragma unroll
            for (int p = 0; p < 2; p++) {
                if (transB) {
                    unsigned off = (unsigned)(((wn + 16 * p + bt_row) * BPT + kb + bt_cs) * 2);
                    LDSM4(bh[2 * p][0], bh[2 * p][1], bh[2 * p + 1][0], bh[2 * p + 1][1], baseBh + off);
                    LDSM4(blr[2 * p][0], blr[2 * p][1], blr[2 * p + 1][0], blr[2 * p + 1][1], baseBl + off);
                } else {
                    unsigned off = (unsigned)(((kb + bn_row) * BPN + wn + 16 * p + bn_cs) * 2);
                    LDSM4T(bh[2 * p][0], bh[2 * p][1], bh[2 * p + 1][0], bh[2 * p + 1][1], baseBh + off);
                    LDSM4T(blr[2 * p][0], blr[2 * p][1], blr[2 * p + 1][0], blr[2 * p + 1][1], baseBl + off);
                }
            }
#pragma unroll
            for (int mi = 0; mi < 2; mi++)
#pragma unroll
                for (int j = 0; j < 4; j++) {
                    mma_bf16(acc[mi][j], ah[mi], bh[j][0], bh[j][1]);
                    mma_bf16(acc[mi][j], ah[mi], blr[j][0], blr[j][1]);
                    mma_bf16(acc[mi][j], alr[mi], bh[j][0], bh[j][1]);
                }
        }
        __syncthreads();
    }

#pragma unroll
    for (int mi = 0; mi < 2; mi++)
#pragma unroll
        for (int j = 0; j < 4; j++) {
            int col = n0 + wn + (j << 3) + cc2;
            int row = m0 + wm + (mi << 4) + gg;
            float b0v = bias ? bias[col] : 0.f;
            float b1v = bias ? bias[col + 1] : 0.f;
            float v00 = acc[mi][j][0] + b0v, v01 = acc[mi][j][1] + b1v;
            float v10 = acc[mi][j][2] + b0v, v11 = acc[mi][j][3] + b1v;
            float *p0 = C + (long long)row * ldc + col;
            float *p1 = C + (long long)(row + 8) * ldc + col;
            if (ep == 1) {
                v00 = gelu_exact(v00); v01 = gelu_exact(v01);
                v10 = gelu_exact(v10); v11 = gelu_exact(v11);
            } else if (ep == 2) {
                v00 += p0[0]; v01 += p0[1]; v10 += p1[0]; v11 += p1[1];
            }
            p0[0] = v00; p0[1] = v01; p1[0] = v10; p1[1] = v11;
        }
}

__global__ void embed_kernel(const int *__restrict__ idx, const float *__restrict__ tok,
                             const float *__restrict__ pos, float *__restrict__ x)
{
    int i = blockIdx.x * 256 + threadIdx.x;
    if (i >= MM * CC) return;
    int c = i & (CC - 1);
    int bt = i >> 9;
    int tp = bt & (TT - 1);
    x[i] = tok[idx[bt] * CC + c] + pos[tp * CC + c];
}

__global__ __launch_bounds__(256)
void ln_kernel(const float *__restrict__ x, float *__restrict__ o,
               const float *__restrict__ gam, const float *__restrict__ bet)
{
    __shared__ float red[256];
    int row = blockIdx.x, t = threadIdx.x;
    const float *xr = x + (long long)row * CC;
    float a = xr[t], b = xr[t + 256];
    red[t] = a + b;
    __syncthreads();
    for (int off = 128; off > 0; off >>= 1) {
        if (t < off) red[t] += red[t + off];
        __syncthreads();
    }
    float mu = red[0] * (1.0f / CC);
    __syncthreads();
    float da = a - mu, db = b - mu;
    red[t] = da * da + db * db;
    __syncthreads();
    for (int off = 128; off > 0; off >>= 1) {
        if (t < off) red[t] += red[t + off];
        __syncthreads();
    }
    float rstd = rsqrtf(red[0] * (1.0f / CC) + 1e-5f);
    float *orow = o + (long long)row * CC;
    orow[t]       = da * rstd * gam[t] + bet[t];
    orow[t + 256] = db * rstd * gam[t + 256] + bet[t + 256];
}

__global__ __launch_bounds__(128)
void softmax_kernel(float *__restrict__ att)
{
    __shared__ float red[128];
    int row = blockIdx.x, t = threadIdx.x;
    float *p = att + (long long)row * TT;
    float v[4];
    float m = -1e30f;
#pragma unroll
    for (int i = 0; i < 4; i++) { v[i] = p[t + (i << 7)] * 0.125f; m = fmaxf(m, v[i]); }
    red[t] = m; __syncthreads();
    for (int off = 64; off > 0; off >>= 1) {
        if (t < off) red[t] = fmaxf(red[t], red[t + off]);
        __syncthreads();
    }
    m = red[0]; __syncthreads();
    float s = 0.f;
#pragma unroll
    for (int i = 0; i < 4; i++) { v[i] = __expf(v[i] - m); s += v[i]; }
    red[t] = s; __syncthreads();
    for (int off = 64; off > 0; off >>= 1) {
        if (t < off) red[t] += red[t + off];
        __syncthreads();
    }
    float inv = 1.0f / red[0];
#pragma unroll
    for (int i = 0; i < 4; i++) p[t + (i << 7)] = v[i] * inv;
}

static inline void run_gemm(const float *A, int lda, long long sA0, long long sA1,
                            const float *B, int ldb, long long sB0, long long sB1,
                            float *C, int ldc, long long sC0, long long sC1,
                            int Mr, int Nc, int K, int zdiv, int batches,
                            const float *bias, int transB, int ep)
{
    dim3 grid(Nc / 64, Mr / 128, batches);
    gemm_kernel<<<grid, 256>>>(A, lda, sA0, sA1, B, ldb, sB0, sB1,
                               C, ldc, sC0, sC1, K, zdiv, bias, transB, ep);
}

extern "C" void kernel_launch(void *const *d_in, const int *in_sizes, int n_in,
                              void *d_out, int out_size)
{
    (void)in_sizes; (void)n_in; (void)out_size;
    const int   *idx  = (const int *)d_in[0];
    const float *tok  = (const float *)d_in[1];
    const float *pos  = (const float *)d_in[2];
    const float *ln1g = (const float *)d_in[3];
    const float *ln1b = (const float *)d_in[4];
    const float *Wq   = (const float *)d_in[5];
    const float *bq   = (const float *)d_in[6];
    const float *Wk   = (const float *)d_in[7];
    const float *bk   = (const float *)d_in[8];
    const float *Wv   = (const float *)d_in[9];
    const float *bv   = (const float *)d_in[10];
    const float *Wp   = (const float *)d_in[11];
    const float *bp   = (const float *)d_in[12];
    const float *ln2g = (const float *)d_in[13];
    const float *ln2b = (const float *)d_in[14];
    const float *W1   = (const float *)d_in[15];
    const float *b1   = (const float *)d_in[16];
    const float *W2   = (const float *)d_in[17];
    const float *b2   = (const float *)d_in[18];
    const float *lnfg = (const float *)d_in[19];
    const float *lnfb = (const float *)d_in[20];
    const float *Wh   = (const float *)d_in[21];
    float *out = (float *)d_out;

    float *S = nullptr;
    cudaGetSymbolAddress((void **)&S, g_scratch);
    float *x = S + O_X, *xn = S + O_XN, *q = S + O_Q, *k = S + O_K;
    float *v = S + O_V, *y = S + O_Y, *h = S + O_H, *att = S + O_ATT;

    embed_kernel<<<(MM * CC + 255) / 256, 256>>>(idx, tok, pos, x);

    const long long TC = (long long)TT * CC;
    const long long T2 = (long long)TT * TT;
    const long long HT2 = (long long)HH * T2;
    const long long CC2 = (long long)CC * CC;

    for (int s = 0; s < STEPS; s++) {
        for (int l = 0; l < LL; l++) {
            ln_kernel<<<MM, 256>>>(x, xn, ln1g + l * CC, ln1b + l * CC);
            run_gemm(xn, CC, 0, 0, Wq + l * CC2, CC, 0, 0, q, CC, 0, 0,
                     MM, CC, CC, 1, 1, bq + l * CC, 0, 0);
            run_gemm(xn, CC, 0, 0, Wk + l * CC2, CC, 0, 0, k, CC, 0, 0,
                     MM, CC, CC, 1, 1, bk + l * CC, 0, 0);
            run_gemm(xn, CC, 0, 0, Wv + l * CC2, CC, 0, 0, v, CC, 0, 0,
                     MM, CC, CC, 1, 1, bv + l * CC, 0, 0);
            // scores = Q @ K^T per (b,h): z = b*H + h
            run_gemm(q, CC, TC, DHD, k, CC, TC, DHD, att, TT, HT2, T2,
                     TT, TT, DHD, HH, BQ * HH, nullptr, 1, 0);
            softmax_kernel<<<BQ * HH * TT, 128>>>(att);
            // y = P @ V
            run_gemm(att, TT, HT2, T2, v, CC, TC, DHD, y, CC, TC, DHD,
                     TT, DHD, TT, HH, BQ * HH, nullptr, 0, 0);
            // x += y @ Wp + bp
            run_gemm(y, CC, 0, 0, Wp + l * CC2, CC, 0, 0, x, CC, 0, 0,
                     MM, CC, CC, 1, 1, bp + l * CC, 0, 2);
            ln_kernel<<<MM, 256>>>(x, xn, ln2g + l * CC, ln2b + l * CC);
            // h = gelu(xn @ W1 + b1)
            run_gemm(xn, CC, 0, 0, W1 + (long long)l * CC * 4 * CC, 4 * CC, 0, 0,
                     h, 4 * CC, 0, 0, MM, 4 * CC, CC, 1, 1, b1 + l * 4 * CC, 0, 1);
            // x += h @ W2 + b2
            run_gemm(h, 4 * CC, 0, 0, W2 + (long long)l * 4 * CC * CC, CC, 0, 0,
                     x, CC, 0, 0, MM, CC, 4 * CC, 1, 1, b2 + l * CC, 0, 2);
        }
    }
    ln_kernel<<<MM, 256>>>(x, xn, lnfg, lnfb);
    run_gemm(xn, CC, 0, 0, Wh, CC, 0, 0, out, CC, 0, 0,
             MM, CC, CC, 1, 1, nullptr, 0, 0);
}

// round 7
// speedup vs baseline: 1.6552x; 1.1057x over previous
#include <cuda_runtime.h>
#include <cuda_bf16.h>
#include <math.h>
#include <stdint.h>

#define BQ 8
#define TT 512
#define CC 512
#define HH 8
#define DHD 64
#define LL 2
#define MM (BQ * TT)
#define FF (4 * CC)
#define STEPS 4
typedef __nv_bfloat16 bf16;
typedef long long ll;

// ------------------------- scratch (__device__ globals) --------------------
__device__ __align__(16) float g_x[MM * CC];
__device__ __align__(16) float g_att[BQ * HH * TT * TT];
__device__ __align__(16) bf16 g_xnh[MM * CC], g_xnl[MM * CC];
__device__ __align__(16) bf16 g_qh[MM * CC],  g_ql[MM * CC];
__device__ __align__(16) bf16 g_kh[MM * CC],  g_kl[MM * CC];
__device__ __align__(16) bf16 g_vh[MM * CC],  g_vl[MM * CC];
__device__ __align__(16) bf16 g_yh[MM * CC],  g_yl[MM * CC];
__device__ __align__(16) bf16 g_hh[MM * FF],  g_hl[MM * FF];
__device__ __align__(16) bf16 g_ph[BQ * HH * TT * TT], g_pl[BQ * HH * TT * TT];
#define NW 6553600
__device__ __align__(16) bf16 g_wh[NW], g_wl[NW];
#define WOFF_L  3145728
#define WOFF_Q  0
#define WOFF_K  262144
#define WOFF_V  524288
#define WOFF_P  786432
#define WOFF_1  1048576
#define WOFF_2  2097152
#define WOFF_HD 6291456

// ------------------------- helpers -----------------------------------------
__device__ __forceinline__ void split1(float v, bf16 &h, bf16 &l) {
    h = __float2bfloat16(v);
    l = __float2bfloat16(v - __bfloat162float(h));
}
__device__ __forceinline__ void split2(float x, float y, unsigned &hi, unsigned &lo) {
    bf16 hx, lx, hy, ly;
    split1(x, hx, lx); split1(y, hy, ly);
    hi = ((unsigned)__bfloat16_as_ushort(hy) << 16) | (unsigned)__bfloat16_as_ushort(hx);
    lo = ((unsigned)__bfloat16_as_ushort(ly) << 16) | (unsigned)__bfloat16_as_ushort(lx);
}
__device__ __forceinline__ unsigned smem_u32(const void *p) {
    return (unsigned)__cvta_generic_to_shared(p);
}
__device__ __forceinline__ float gelu_exact(float x) {
    return 0.5f * x * (1.0f + erff(x * 0.7071067811865476f));
}
__device__ __forceinline__ void mma_bf16(float *d, const unsigned *a, unsigned b0, unsigned b1) {
    asm volatile(
        "mma.sync.aligned.m16n8k16.row.col.f32.bf16.bf16.f32 "
        "{%0,%1,%2,%3}, {%4,%5,%6,%7}, {%8,%9}, {%0,%1,%2,%3};\n"
        : "+f"(d[0]), "+f"(d[1]), "+f"(d[2]), "+f"(d[3])
        : "r"(a[0]), "r"(a[1]), "r"(a[2]), "r"(a[3]), "r"(b0), "r"(b1));
}
#define LDSM4(R0, R1, R2, R3, ADDR) \
    asm volatile("ldmatrix.sync.aligned.m8n8.x4.shared.b16 {%0,%1,%2,%3}, [%4];" \
                 : "=r"(R0), "=r"(R1), "=r"(R2), "=r"(R3) : "r"(ADDR))
#define LDSM4T(R0, R1, R2, R3, ADDR) \
    asm volatile("ldmatrix.sync.aligned.m8n8.x4.trans.shared.b16 {%0,%1,%2,%3}, [%4];" \
                 : "=r"(R0), "=r"(R1), "=r"(R2), "=r"(R3) : "r"(ADDR))
#define CP16(dst, src) \
    asm volatile("cp.async.cg.shared.global [%0], [%1], 16;" :: "r"(dst), "l"(src))
#define CP_COMMIT() asm volatile("cp.async.commit_group;" ::: "memory")
#define CP_WAIT1()  asm volatile("cp.async.wait_group 1;" ::: "memory")
#define CP_WAIT0()  asm volatile("cp.async.wait_group 0;" ::: "memory")

// ------------------------- HMMA GEMM (pure bf16, double-buffered) ----------
// D[M,N] = Ahi@Bhi + Ahi@Blo + Alo@Bhi (+bias). A K-major [m][k].
// transB=1: B [N,K] rows (C=A@B^T, direct ldmatrix); transB=0: B [K,N] (trans).
// Tile 128x64xK32, 8 warps (warp 32x32), cp.async double buffer.
// ep: 0 Cf=acc+bias; 1 Coh/Col=split(gelu(acc+bias)); 2 Cf+=acc+bias; 3 split.
#define APITCH 40
#define BPT    40
#define BPN    72
// smem element offsets (bf16): A hi: buf*5120; A lo: 10240+buf*5120;
// B hi: 20480+buf*2560; B lo: 25600+buf*2560. Total 30720 elems = 61440 B.
#define SMEM_BYTES 61440

__global__ __launch_bounds__(256, 2)
void gemm_hmma(const bf16 *__restrict__ Ah_, const bf16 *__restrict__ Al_, int lda,
               ll sA0, ll sA1,
               const bf16 *__restrict__ Bh_, const bf16 *__restrict__ Bl_, int ldb,
               ll sB0, ll sB1,
               float *__restrict__ Cf, bf16 *__restrict__ Coh, bf16 *__restrict__ Col,
               int ldc, ll sC0, ll sC1,
               int K, int zdiv, const float *__restrict__ bias, int transB, int ep)
{
    extern __shared__ __align__(16) bf16 sm[];
    int z = blockIdx.z;
    ll zo0 = z / zdiv, zo1 = z % zdiv;
    Ah_ += zo0 * sA0 + zo1 * sA1;  Al_ += zo0 * sA0 + zo1 * sA1;
    Bh_ += zo0 * sB0 + zo1 * sB1;  Bl_ += zo0 * sB0 + zo1 * sB1;
    ll coff = zo0 * sC0 + zo1 * sC1;
    int n0 = blockIdx.x * 64, m0 = blockIdx.y * 128;

    int t = threadIdx.x, lane = t & 31, warp = t >> 5;
    int wm = (warp & 3) << 5, wn = (warp >> 2) << 5;
    int gg = lane >> 2, cc2 = (lane & 3) << 1;

    // cp.async indices
    int a_ck = (t & 3) << 3, a_rw = t >> 2;            // A: 64 rows/pass, 4 chunks
    int bt_rw = t >> 2, bt_ck = (t & 3) << 3;          // B [N,K]: 64 rows
    int bn_rw = t >> 3, bn_ck = (t & 7) << 3;          // B [K,N]: 32 rows x 8 chunks

    unsigned sb = smem_u32(sm);

    // ldmatrix per-lane geometry
    int sel = lane >> 3, lr = lane & 7;
    int ar_g = lr + ((sel & 1) ? 8 : 0);
    int a_cs = (sel & 2) ? 8 : 0;
    int btr_g = lr + ((sel & 2) ? 8 : 0);
    int bt_cs = (sel & 1) ? 8 : 0;
    int bnr_g = lr + ((sel & 1) ? 8 : 0);
    int bn_cs = (sel & 2) ? 8 : 0;

    float acc[2][4][4];
#pragma unroll
    for (int mi = 0; mi < 2; mi++)
#pragma unroll
        for (int j = 0; j < 4; j++)
#pragma unroll
            for (int r = 0; r < 4; r++) acc[mi][j][r] = 0.f;

#define ISSUE(BUF, K0) do { \
    unsigned aoh = sb + ((BUF) * 5120) * 2, aol = sb + (10240 + (BUF) * 5120) * 2; \
    _Pragma("unroll") \
    for (int p = 0; p < 2; p++) { \
        int row = a_rw + 64 * p; \
        ll go = (ll)(m0 + row) * lda + (K0) + a_ck; \
        unsigned d = (unsigned)((row * APITCH + a_ck) * 2); \
        CP16(aoh + d, Ah_ + go); \
        CP16(aol + d, Al_ + go); \
    } \
    unsigned boh = sb + (20480 + (BUF) * 2560) * 2, bol = sb + (25600 + (BUF) * 2560) * 2; \
    if (transB) { \
        ll go = (ll)(n0 + bt_rw) * ldb + (K0) + bt_ck; \
        unsigned d = (unsigned)((bt_rw * BPT + bt_ck) * 2); \
        CP16(boh + d, Bh_ + go); \
        CP16(bol + d, Bl_ + go); \
    } else { \
        ll go = (ll)((K0) + bn_rw) * ldb + n0 + bn_ck; \
        unsigned d = (unsigned)((bn_rw * BPN + bn_ck) * 2); \
        CP16(boh + d, Bh_ + go); \
        CP16(bol + d, Bl_ + go); \
    } \
    CP_COMMIT(); \
} while (0)

    int nk = K >> 5;
    ISSUE(0, 0);
    for (int c = 0; c < nk; c++) {
        if (c + 1 < nk) { ISSUE((c + 1) & 1, (c + 1) << 5); CP_WAIT1(); }
        else CP_WAIT0();
        __syncthreads();

        unsigned aoh = sb + ((c & 1) * 5120) * 2;
        unsigned aol = sb + (10240 + (c & 1) * 5120) * 2;
        unsigned boh = sb + (20480 + (c & 1) * 2560) * 2;
        unsigned bol = sb + (25600 + (c & 1) * 2560) * 2;
#pragma unroll
        for (int ks = 0; ks < 2; ks++) {
            int kb = ks << 4;
            unsigned ah[2][4], al2[2][4];
#pragma unroll
            for (int mi = 0; mi < 2; mi++) {
                unsigned off = (unsigned)(((wm + 16 * mi + ar_g) * APITCH + kb + a_cs) * 2);
                LDSM4(ah[mi][0], ah[mi][1], ah[mi][2], ah[mi][3], aoh + off);
                LDSM4(al2[mi][0], al2[mi][1], al2[mi][2], al2[mi][3], aol + off);
            }
            unsigned bh[4][2], bl2[4][2];
#pragma unroll
            for (int p = 0; p < 2; p++) {
                if (transB) {
                    unsigned off = (unsigned)(((wn + 16 * p + btr_g) * BPT + kb + bt_cs) * 2);
                    LDSM4(bh[2 * p][0], bh[2 * p][1], bh[2 * p + 1][0], bh[2 * p + 1][1], boh + off);
                    LDSM4(bl2[2 * p][0], bl2[2 * p][1], bl2[2 * p + 1][0], bl2[2 * p + 1][1], bol + off);
                } else {
                    unsigned off = (unsigned)(((kb + bnr_g) * BPN + wn + 16 * p + bn_cs) * 2);
                    LDSM4T(bh[2 * p][0], bh[2 * p][1], bh[2 * p + 1][0], bh[2 * p + 1][1], boh + off);
                    LDSM4T(bl2[2 * p][0], bl2[2 * p][1], bl2[2 * p + 1][0], bl2[2 * p + 1][1], bol + off);
                }
            }
#pragma unroll
            for (int mi = 0; mi < 2; mi++)
#pragma unroll
                for (int j = 0; j < 4; j++) {
                    mma_bf16(acc[mi][j], ah[mi], bh[j][0], bh[j][1]);
                    mma_bf16(acc[mi][j], ah[mi], bl2[j][0], bl2[j][1]);
                    mma_bf16(acc[mi][j], al2[mi], bh[j][0], bh[j][1]);
                }
        }
        __syncthreads();
    }

#pragma unroll
    for (int mi = 0; mi < 2; mi++)
#pragma unroll
        for (int j = 0; j < 4; j++) {
            int col = n0 + wn + (j << 3) + cc2;
            int row = m0 + wm + (mi << 4) + gg;
            float b0v = bias ? bias[col] : 0.f;
            float b1v = bias ? bias[col + 1] : 0.f;
            float v00 = acc[mi][j][0] + b0v, v01 = acc[mi][j][1] + b1v;
            float v10 = acc[mi][j][2] + b0v, v11 = acc[mi][j][3] + b1v;
            ll g0 = (ll)row * ldc + col + coff;
            ll g1 = (ll)(row + 8) * ldc + col + coff;
            if (ep == 0) {
                *(float2 *)(Cf + g0) = make_float2(v00, v01);
                *(float2 *)(Cf + g1) = make_float2(v10, v11);
            } else if (ep == 2) {
                float2 o0 = *(float2 *)(Cf + g0), o1 = *(float2 *)(Cf + g1);
                *(float2 *)(Cf + g0) = make_float2(o0.x + v00, o0.y + v01);
                *(float2 *)(Cf + g1) = make_float2(o1.x + v10, o1.y + v11);
            } else {
                if (ep == 1) {
                    v00 = gelu_exact(v00); v01 = gelu_exact(v01);
                    v10 = gelu_exact(v10); v11 = gelu_exact(v11);
                }
                unsigned hi, lo;
                split2(v00, v01, hi, lo);
                *(unsigned *)(Coh + g0) = hi; *(unsigned *)(Col + g0) = lo;
                split2(v10, v11, hi, lo);
                *(unsigned *)(Coh + g1) = hi; *(unsigned *)(Col + g1) = lo;
            }
        }
}

// ------------------------- one-time weight transpose+split -----------------
__global__ __launch_bounds__(256)
void wconv_kernel(const float *__restrict__ W, bf16 *__restrict__ th,
                  bf16 *__restrict__ tl, int K, int N)
{
    __shared__ float tile[32][33];
    int bx = blockIdx.x * 32, by = blockIdx.y * 32;
    int tx = threadIdx.x & 31, ty = threadIdx.x >> 5;
#pragma unroll
    for (int j = 0; j < 4; j++) {
        int kk = ty + j * 8;
        tile[kk][tx] = W[(ll)(by + kk) * N + bx + tx];
    }
    __syncthreads();
#pragma unroll
    for (int j = 0; j < 4; j++) {
        int nn = ty + j * 8;
        float v = tile[tx][nn];
        bf16 h, l;
        split1(v, h, l);
        ll o = (ll)(bx + nn) * K + by + tx;
        th[o] = h; tl[o] = l;
    }
}

// ------------------------- element kernels ---------------------------------
__global__ void embed_kernel(const int *__restrict__ idx, const float *__restrict__ tok,
                             const float *__restrict__ pos, float *__restrict__ x)
{
    int i = blockIdx.x * 256 + threadIdx.x;
    if (i >= MM * CC) return;
    int c = i & (CC - 1);
    int bt = i >> 9;
    int tp = bt & (TT - 1);
    x[i] = tok[idx[bt] * CC + c] + pos[tp * CC + c];
}

__global__ __launch_bounds__(256)
void ln_kernel(const float *__restrict__ x, bf16 *__restrict__ oh, bf16 *__restrict__ ol,
               const float *__restrict__ gam, const float *__restrict__ bet)
{
    __shared__ float red[256];
    int row = blockIdx.x, t = threadIdx.x;
    const float *xr = x + (ll)row * CC;
    float a = xr[t], b = xr[t + 256];
    red[t] = a + b;
    __syncthreads();
    for (int off = 128; off > 0; off >>= 1) {
        if (t < off) red[t] += red[t + off];
        __syncthreads();
    }
    float mu = red[0] * (1.0f / CC);
    __syncthreads();
    float da = a - mu, db = b - mu;
    red[t] = da * da + db * db;
    __syncthreads();
    for (int off = 128; off > 0; off >>= 1) {
        if (t < off) red[t] += red[t + off];
        __syncthreads();
    }
    float rstd = rsqrtf(red[0] * (1.0f / CC) + 1e-5f);
    float r0 = da * rstd * gam[t] + bet[t];
    float r1 = db * rstd * gam[t + 256] + bet[t + 256];
    bf16 h, l;
    ll o = (ll)row * CC;
    split1(r0, h, l); oh[o + t] = h;       ol[o + t] = l;
    split1(r1, h, l); oh[o + t + 256] = h; ol[o + t + 256] = l;
}

__global__ __launch_bounds__(128)
void softmax_kernel(const float *__restrict__ att, bf16 *__restrict__ ph,
                    bf16 *__restrict__ pl)
{
    __shared__ float red[128];
    int row = blockIdx.x, t = threadIdx.x;
    const float *p = att + (ll)row * TT;
    float v[4];
    float m = -1e30f;
#pragma unroll
    for (int i = 0; i < 4; i++) { v[i] = p[t + (i << 7)] * 0.125f; m = fmaxf(m, v[i]); }
    red[t] = m; __syncthreads();
    for (int off = 64; off > 0; off >>= 1) {
        if (t < off) red[t] = fmaxf(red[t], red[t + off]);
        __syncthreads();
    }
    m = red[0]; __syncthreads();
    float s = 0.f;
#pragma unroll
    for (int i = 0; i < 4; i++) { v[i] = __expf(v[i] - m); s += v[i]; }
    red[t] = s; __syncthreads();
    for (int off = 64; off > 0; off >>= 1) {
        if (t < off) red[t] += red[t + off];
        __syncthreads();
    }
    float inv = 1.0f / red[0];
    ll o = (ll)row * TT;
#pragma unroll
    for (int i = 0; i < 4; i++) {
        bf16 h, l;
        split1(v[i] * inv, h, l);
        ph[o + t + (i << 7)] = h;
        pl[o + t + (i << 7)] = l;
    }
}

// ------------------------- host orchestration ------------------------------
static void run_hm(const bf16 *Ah, const bf16 *Al, int lda, ll sA0, ll sA1,
                   const bf16 *Bh, const bf16 *Bl, int ldb, ll sB0, ll sB1,
                   float *Cf, bf16 *Coh, bf16 *Col, int ldc, ll sC0, ll sC1,
                   int Mr, int Nc, int K, int zdiv, int Z,
                   const float *bias, int transB, int ep)
{
    dim3 g(Nc / 64, Mr / 128, Z);
    gemm_hmma<<<g, 256, SMEM_BYTES>>>(Ah, Al, lda, sA0, sA1, Bh, Bl, ldb, sB0, sB1,
                                      Cf, Coh, Col, ldc, sC0, sC1, K, zdiv, bias, transB, ep);
}

extern "C" void kernel_launch(void *const *d_in, const int *in_sizes, int n_in,
                              void *d_out, int out_size)
{
    (void)in_sizes; (void)n_in; (void)out_size;
    const int   *idx  = (const int *)d_in[0];
    const float *tok  = (const float *)d_in[1];
    const float *pos  = (const float *)d_in[2];
    const float *ln1g = (const float *)d_in[3];
    const float *ln1b = (const float *)d_in[4];
    const float *Wq   = (const float *)d_in[5];
    const float *bq   = (const float *)d_in[6];
    const float *Wk   = (const float *)d_in[7];
    const float *bk   = (const float *)d_in[8];
    const float *Wv   = (const float *)d_in[9];
    const float *bv   = (const float *)d_in[10];
    const float *Wp   = (const float *)d_in[11];
    const float *bp   = (const float *)d_in[12];
    const float *ln2g = (const float *)d_in[13];
    const float *ln2b = (const float *)d_in[14];
    const float *W1   = (const float *)d_in[15];
    const float *b1   = (const float *)d_in[16];
    const float *W2   = (const float *)d_in[17];
    const float *b2   = (const float *)d_in[18];
    const float *lnfg = (const float *)d_in[19];
    const float *lnfb = (const float *)d_in[20];
    const float *Wh   = (const float *)d_in[21];
    float *out = (float *)d_out;

    static int smem_set = 0;
    if (!smem_set) {
        cudaFuncSetAttribute(gemm_hmma, cudaFuncAttributeMaxDynamicSharedMemorySize, SMEM_BYTES);
        smem_set = 1;
    }

    float *x, *att;
    bf16 *xnh, *xnl, *qh, *ql, *kh, *kl, *vh, *vl, *yh, *yl, *hh, *hl, *ph, *pl, *wh, *wl;
    cudaGetSymbolAddress((void **)&x, g_x);
    cudaGetSymbolAddress((void **)&att, g_att);
    cudaGetSymbolAddress((void **)&xnh, g_xnh); cudaGetSymbolAddress((void **)&xnl, g_xnl);
    cudaGetSymbolAddress((void **)&qh, g_qh);   cudaGetSymbolAddress((void **)&ql, g_ql);
    cudaGetSymbolAddress((void **)&kh, g_kh);   cudaGetSymbolAddress((void **)&kl, g_kl);
    cudaGetSymbolAddress((void **)&vh, g_vh);   cudaGetSymbolAddress((void **)&vl, g_vl);
    cudaGetSymbolAddress((void **)&yh, g_yh);   cudaGetSymbolAddress((void **)&yl, g_yl);
    cudaGetSymbolAddress((void **)&hh, g_hh);   cudaGetSymbolAddress((void **)&hl, g_hl);
    cudaGetSymbolAddress((void **)&ph, g_ph);   cudaGetSymbolAddress((void **)&pl, g_pl);
    cudaGetSymbolAddress((void **)&wh, g_wh);   cudaGetSymbolAddress((void **)&wl, g_wl);

    dim3 tb(256);
    for (int l = 0; l < LL; l++) {
        ll wb = (ll)l * WOFF_L;
        wconv_kernel<<<dim3(CC / 32, CC / 32), tb>>>(Wq + l * CC * CC, wh + wb + WOFF_Q, wl + wb + WOFF_Q, CC, CC);
        wconv_kernel<<<dim3(CC / 32, CC / 32), tb>>>(Wk + l * CC * CC, wh + wb + WOFF_K, wl + wb + WOFF_K, CC, CC);
        wconv_kernel<<<dim3(CC / 32, CC / 32), tb>>>(Wv + l * CC * CC, wh + wb + WOFF_V, wl + wb + WOFF_V, CC, CC);
        wconv_kernel<<<dim3(CC / 32, CC / 32), tb>>>(Wp + l * CC * CC, wh + wb + WOFF_P, wl + wb + WOFF_P, CC, CC);
        wconv_kernel<<<dim3(FF / 32, CC / 32), tb>>>(W1 + (ll)l * CC * FF, wh + wb + WOFF_1, wl + wb + WOFF_1, CC, FF);
        wconv_kernel<<<dim3(CC / 32, FF / 32), tb>>>(W2 + (ll)l * FF * CC, wh + wb + WOFF_2, wl + wb + WOFF_2, FF, CC);
    }
    wconv_kernel<<<dim3(CC / 32, CC / 32), tb>>>(Wh, wh + WOFF_HD, wl + WOFF_HD, CC, CC);

    embed_kernel<<<(MM * CC + 255) / 256, 256>>>(idx, tok, pos, x);

    const ll TC = (ll)TT * CC;
    const ll T2 = (ll)TT * TT;

    for (int s = 0; s < STEPS; s++) {
        for (int l = 0; l < LL; l++) {
            ll wb = (ll)l * WOFF_L;
            ln_kernel<<<MM, 256>>>(x, xnh, xnl, ln1g + l * CC, ln1b + l * CC);
            run_hm(xnh, xnl, CC, 0, 0, wh + wb + WOFF_Q, wl + wb + WOFF_Q, CC, 0, 0,
                   nullptr, qh, ql, CC, 0, 0, MM, CC, CC, 1, 1, bq + l * CC, 1, 3);
            run_hm(xnh, xnl, CC, 0, 0, wh + wb + WOFF_K, wl + wb + WOFF_K, CC, 0, 0,
                   nullptr, kh, kl, CC, 0, 0, MM, CC, CC, 1, 1, bk + l * CC, 1, 3);
            run_hm(xnh, xnl, CC, 0, 0, wh + wb + WOFF_V, wl + wb + WOFF_V, CC, 0, 0,
                   nullptr, vh, vl, CC, 0, 0, MM, CC, CC, 1, 1, bv + l * CC, 1, 3);
            // scores[b,h] = Q @ K^T
            run_hm(qh, ql, CC, TC, DHD, kh, kl, CC, TC, DHD,
                   att, nullptr, nullptr, TT, (ll)HH * T2, T2,
                   TT, TT, DHD, HH, BQ * HH, nullptr, 1, 0);
            softmax_kernel<<<BQ * HH * TT, 128>>>(att, ph, pl);
            // y = P @ V
            run_hm(ph, pl, TT, (ll)HH * T2, T2, vh, vl, CC, TC, DHD,
                   nullptr, yh, yl, CC, TC, DHD,
                   TT, DHD, TT, HH, BQ * HH, nullptr, 0, 3);
            // x += y @ Wp + bp
            run_hm(yh, yl, CC, 0, 0, wh + wb + WOFF_P, wl + wb + WOFF_P, CC, 0, 0,
                   x, nullptr, nullptr, CC, 0, 0, MM, CC, CC, 1, 1, bp + l * CC, 1, 2);
            ln_kernel<<<MM, 256>>>(x, xnh, xnl, ln2g + l * CC, ln2b + l * CC);
            // h = gelu(xn @ W1 + b1)
            run_hm(xnh, xnl, CC, 0, 0, wh + wb + WOFF_1, wl + wb + WOFF_1, CC, 0, 0,
                   nullptr, hh, hl, FF, 0, 0, MM, FF, CC, 1, 1, b1 + l * FF, 1, 1);
            // x += h @ W2 + b2
            run_hm(hh, hl, FF, 0, 0, wh + wb + WOFF_2, wl + wb + WOFF_2, FF, 0, 0,
                   x, nullptr, nullptr, CC, 0, 0, MM, CC, FF, 1, 1, b2 + l * CC, 1, 2);
        }
    }
    ln_kernel<<<MM, 256>>>(x, xnh, xnl, lnfg, lnfb);
    run_hm(xnh, xnl, CC, 0, 0, wh + WOFF_HD, wl + WOFF_HD, CC, 0, 0,
           out, nullptr, nullptr, CC, 0, 0, MM, CC, CC, 1, 1, nullptr, 1, 0);
}